// round 16
// baseline (speedup 1.0000x reference)
#include <cuda_runtime.h>
#include <cuda_bf16.h>
#include <math.h>

#define DIM     4096
#define NHEADS  32
#define HD      128
#define BSZ     8
#define SEQ     512
#define START_P 512
#define KVLEN   1024
#define NTOK    (BSZ*SEQ)   /* 4096 tokens */
#define MAXSEQ  2048

// Scratch (device globals; no runtime allocation allowed)
__device__ float g_q[(size_t)NTOK * DIM];
__device__ float g_k[(size_t)NTOK * DIM];
__device__ float g_v[(size_t)NTOK * DIM];
__device__ float g_attn[(size_t)NTOK * DIM];
// tf32-pre-rounded operands
__device__ float g_xr[(size_t)NTOK * DIM];
__device__ float g_wqkvr[(size_t)3 * DIM * DIM];   // [wq; wk; wv] concat, rounded
__device__ float g_wor[(size_t)DIM * DIM];
// merged + tf32-rounded K/V for attention (+ transposed V), router mask
__device__ float g_kc[(size_t)BSZ * NHEADS * KVLEN * HD];
__device__ float g_vc[(size_t)BSZ * NHEADS * KVLEN * HD];
__device__ float g_vt[(size_t)BSZ * NHEADS * HD * KVLEN];   // [b][h][d][kv]
__device__ float g_radd[(size_t)BSZ * KVLEN];

// ---------------------------------------------------------------------------
// TF32 / async helpers
// ---------------------------------------------------------------------------
__device__ __forceinline__ float tf32r(float x) {
    float y;
    asm("cvt.rna.tf32.f32 %0, %1;" : "=f"(y) : "f"(x));
    return y;
}

__device__ __forceinline__ void mma_tf32(float* c, const unsigned* a, const unsigned* b) {
    asm volatile(
        "mma.sync.aligned.m16n8k8.row.col.f32.tf32.tf32.f32 "
        "{%0,%1,%2,%3}, {%4,%5,%6,%7}, {%8,%9}, {%0,%1,%2,%3};"
        : "+f"(c[0]), "+f"(c[1]), "+f"(c[2]), "+f"(c[3])
        : "r"(a[0]), "r"(a[1]), "r"(a[2]), "r"(a[3]),
          "r"(b[0]), "r"(b[1]));
}

__device__ __forceinline__ void ldsm_x4(unsigned& r0, unsigned& r1,
                                        unsigned& r2, unsigned& r3,
                                        unsigned saddr) {
    asm volatile(
        "ldmatrix.sync.aligned.m8n8.x4.shared.b16 {%0,%1,%2,%3}, [%4];"
        : "=r"(r0), "=r"(r1), "=r"(r2), "=r"(r3)
        : "r"(saddr));
}

__device__ __forceinline__ void cp_async16(float* smem_dst, const float* gsrc) {
    unsigned saddr = (unsigned)__cvta_generic_to_shared(smem_dst);
    asm volatile("cp.async.cg.shared.global [%0], [%1], 16;\n"
                 :: "r"(saddr), "l"(gsrc));
}
#define CP_COMMIT() asm volatile("cp.async.commit_group;\n" ::: "memory")
#define CP_WAIT1()  asm volatile("cp.async.wait_group 1;\n" ::: "memory")
#define CP_WAIT0()  asm volatile("cp.async.wait_group 0;\n" ::: "memory")

// ---------------------------------------------------------------------------
// Pre-round x, [wq;wk;wv] (into one concat buffer) and wo to tf32.
// ---------------------------------------------------------------------------
__global__ void round5_kernel(
    const float4* __restrict__ x,  const float4* __restrict__ wq,
    const float4* __restrict__ wk, const float4* __restrict__ wv,
    const float4* __restrict__ wo,
    float4* __restrict__ xr, float4* __restrict__ wqkvr,
    float4* __restrict__ wor)
{
    size_t i = (size_t)blockIdx.x * blockDim.x + threadIdx.x;
    const size_t n = (size_t)DIM * DIM / 4;
    if (i >= n) return;
#define R4(dst, src) { float4 v = src[i]; \
    v.x = tf32r(v.x); v.y = tf32r(v.y); v.z = tf32r(v.z); v.w = tf32r(v.w); \
    dst = v; }
    R4(xr[i], x)
    R4(wqkvr[i], wq)
    R4(wqkvr[i + n], wk)
    R4(wqkvr[i + 2 * n], wv)
    R4(wor[i], wo)
#undef R4
}

// ---------------------------------------------------------------------------
// TF32 tensor-core GEMM NT core (R15: ldmatrix fragments; single barrier per
// k-tile; refill after compute; 3-stage cp.async ring). Unchanged.
// ---------------------------------------------------------------------------
#define GEMM_NSTAGE 3
#define GEMM_STAGE_FLOATS (2 * 128 * 32)
#define GEMM_SMEM_BYTES (GEMM_NSTAGE * GEMM_STAGE_FLOATS * 4)  /* 96 KB */

#define GEMM_BODY(A_, B_, K_)                                                  \
    extern __shared__ float sm[];                                              \
    const int tid = threadIdx.x;                                               \
    const int bm = blockIdx.y * 128;                                           \
    const int bn = blockIdx.x * 128;                                           \
    const int warp = tid >> 5, lane = tid & 31;                                \
    const int wm = warp >> 2;                                                  \
    const int wn = warp & 3;                                                   \
    const int grp = lane >> 2;                                                 \
    const int t4 = lane & 3;                                                   \
    const int lq = lane >> 3;                                                  \
    const int lr = lane & 7;                                                   \
    const int a_half = lq & 1;                                                 \
    const int a_chi  = lq >> 1;                                                \
    const int b_nfq  = lq >> 1;                                                \
    const int b_csel = lq & 1;                                                 \
    int abyte[4];                                                              \
    _Pragma("unroll")                                                          \
    for (int mf = 0; mf < 4; mf++)                                             \
        abyte[mf] = (wm * 64 + mf * 16 + a_half * 8 + lr) * 128;               \
    const int bbyte0 = (wn * 32 + b_nfq * 8 + lr) * 128;                       \
    const int bbyte1 = (wn * 32 + (2 + b_nfq) * 8 + lr) * 128;                 \
    int pr[4], pc[4], poff[4];                                                 \
    _Pragma("unroll")                                                          \
    for (int p = 0; p < 4; p++) {                                              \
        int ci = tid + 256 * p;                                                \
        pr[p] = ci >> 3;                                                       \
        pc[p] = ci & 7;                                                        \
        poff[p] = (pr[p] << 5) + ((pc[p] ^ (pr[p] & 7)) << 2);                 \
    }                                                                          \
    float acc[4][4][4];                                                        \
    _Pragma("unroll")                                                          \
    for (int mf = 0; mf < 4; mf++)                                             \
        for (int nf = 0; nf < 4; nf++)                                         \
            for (int r = 0; r < 4; r++) acc[mf][nf][r] = 0.f;                  \
    const int KT = (K_) / 32;                                                  \
    _Pragma("unroll")                                                          \
    for (int s = 0; s < 2; s++) {                                              \
        float* As = sm + s * GEMM_STAGE_FLOATS;                                \
        float* Bs = As + 128 * 32;                                             \
        int k0 = s * 32;                                                       \
        _Pragma("unroll")                                                      \
        for (int p = 0; p < 4; p++) {                                          \
            cp_async16(As + poff[p], (A_) + (size_t)(bm + pr[p]) * (K_) + k0 + pc[p] * 4); \
            cp_async16(Bs + poff[p], (B_) + (size_t)(bn + pr[p]) * (K_) + k0 + pc[p] * 4); \
        }                                                                      \
        CP_COMMIT();                                                           \
    }                                                                          \
    for (int kt = 0; kt < KT; kt++) {                                          \
        CP_WAIT1();                                                            \
        __syncthreads();                                                       \
        const float* Asp = sm + (kt % GEMM_NSTAGE) * GEMM_STAGE_FLOATS;        \
        const unsigned sA = (unsigned)__cvta_generic_to_shared(Asp);           \
        const unsigned sB = sA + 128 * 32 * 4;                                 \
        _Pragma("unroll")                                                      \
        for (int ks = 0; ks < 4; ks++) {                                       \
            const unsigned aoff = (unsigned)(((2 * ks + a_chi) ^ lr) << 4);    \
            const unsigned boff = (unsigned)(((2 * ks + b_csel) ^ lr) << 4);   \
            unsigned af[4][4], bf[4][2];                                       \
            _Pragma("unroll")                                                  \
            for (int mf = 0; mf < 4; mf++)                                     \
                ldsm_x4(af[mf][0], af[mf][1], af[mf][2], af[mf][3],            \
                        sA + abyte[mf] + aoff);                                \
            ldsm_x4(bf[0][0], bf[0][1], bf[1][0], bf[1][1], sB + bbyte0 + boff); \
            ldsm_x4(bf[2][0], bf[2][1], bf[3][0], bf[3][1], sB + bbyte1 + boff); \
            _Pragma("unroll")                                                  \
            for (int mf = 0; mf < 4; mf++)                                     \
                for (int nf = 0; nf < 4; nf++)                                 \
                    mma_tf32(acc[mf][nf], af[mf], bf[nf]);                     \
        }                                                                      \
        if (kt + 2 < KT) {                                                     \
            int s = (kt + 2) % GEMM_NSTAGE;                                    \
            float* Asw = sm + s * GEMM_STAGE_FLOATS;                           \
            float* Bsw = Asw + 128 * 32;                                       \
            int k0 = (kt + 2) * 32;                                            \
            _Pragma("unroll")                                                  \
            for (int p = 0; p < 4; p++) {                                      \
                cp_async16(Asw + poff[p], (A_) + (size_t)(bm + pr[p]) * (K_) + k0 + pc[p] * 4); \
                cp_async16(Bsw + poff[p], (B_) + (size_t)(bn + pr[p]) * (K_) + k0 + pc[p] * 4); \
            }                                                                  \
        }                                                                      \
        CP_COMMIT();                                                           \
    }

__global__ __launch_bounds__(256, 2) void sgemm_tf32_pipe(
    const float* __restrict__ A, const float* __restrict__ B,
    float* __restrict__ C, int M, int N, int K)
{
    GEMM_BODY(A, B, K)
#pragma unroll
    for (int mf = 0; mf < 4; mf++) {
        int row0 = bm + wm * 64 + mf * 16 + grp;
#pragma unroll
        for (int nf = 0; nf < 4; nf++) {
            int col0 = bn + wn * 32 + nf * 8 + t4 * 2;
            float2 v0 = make_float2(acc[mf][nf][0], acc[mf][nf][1]);
            float2 v1 = make_float2(acc[mf][nf][2], acc[mf][nf][3]);
            *(float2*)(C + (size_t)row0 * N + col0) = v0;
            *(float2*)(C + (size_t)(row0 + 8) * N + col0) = v1;
        }
    }
}

__global__ __launch_bounds__(256, 2) void sgemm_tf32_pipe_qkv(
    const float* __restrict__ A, const float* __restrict__ B,
    float* __restrict__ Cq, float* __restrict__ Ck, float* __restrict__ Cv,
    int M, int K)
{
    GEMM_BODY(A, B, K)
    const int which = bn >> 12;
    float* Cw = (which == 0) ? Cq : (which == 1) ? Ck : Cv;
    const int cb = bn & (DIM - 1);
#pragma unroll
    for (int mf = 0; mf < 4; mf++) {
        int row0 = bm + wm * 64 + mf * 16 + grp;
#pragma unroll
        for (int nf = 0; nf < 4; nf++) {
            int col0 = cb + wn * 32 + nf * 8 + t4 * 2;
            float2 v0 = make_float2(acc[mf][nf][0], acc[mf][nf][1]);
            float2 v1 = make_float2(acc[mf][nf][2], acc[mf][nf][3]);
            *(float2*)(Cw + (size_t)row0 * DIM + col0) = v0;
            *(float2*)(Cw + (size_t)(row0 + 8) * DIM + col0) = v1;
        }
    }
}

// ---------------------------------------------------------------------------
// Build merged tf32 K'/V' [b][h][1024][128] + router additive mask.
// ---------------------------------------------------------------------------
__global__ void prep_kv_kernel(
    const float* __restrict__ knew, const float* __restrict__ vnew,
    const float* __restrict__ cache_k, const float* __restrict__ cache_v,
    const float* __restrict__ router,
    float* __restrict__ kc, float* __restrict__ vc, float* __restrict__ radd)
{
    int idx = blockIdx.x * blockDim.x + threadIdx.x;
    const int total = BSZ * NHEADS * KVLEN * 64;
    if (idx >= total) return;
    int i   = idx & 63;
    int pos = (idx >> 6) & (KVLEN - 1);
    int h   = (idx >> 16) & (NHEADS - 1);
    int b   = idx >> 21;

    size_t dst = (((size_t)(b * NHEADS + h)) * KVLEN + pos) * HD + i;
    if (pos < START_P) {
        size_t src = (((size_t)(b * NHEADS + h)) * MAXSEQ + pos) * HD + i;
        kc[dst]      = tf32r(cache_k[src]);
        kc[dst + 64] = tf32r(cache_k[src + 64]);
        vc[dst]      = tf32r(cache_v[src]);
        vc[dst + 64] = tf32r(cache_v[src + 64]);
    } else {
        int s = pos - START_P;
        size_t src = ((size_t)(b * SEQ + s)) * DIM + h * HD + i;
        float freq = exp2f(-(float)i * 0.20762050593045702f);
        float ang = (float)pos * freq;
        float c = cosf(ang), sn = sinf(ang);
        float k0 = knew[src], k1 = knew[src + 64];
        kc[dst]      = tf32r(k0 * c - k1 * sn);
        kc[dst + 64] = tf32r(k1 * c + k0 * sn);
        vc[dst]      = tf32r(vnew[src]);
        vc[dst + 64] = tf32r(vnew[src + 64]);
    }
    if (h == 0 && i == 0) {
        float add = 0.f;
        if (pos >= START_P &&
            router[((size_t)b * SEQ + (pos - START_P)) * 2] == 0.f) add = -1e9f;
        radd[(size_t)b * KVLEN + pos] = add;
    }
}

// ---------------------------------------------------------------------------
// Merged kernel: tiled V transpose (vc [bh][kv][d] -> vt [bh][d][kv]) for
// blocks < 32768, RoPE+scale+tf32 on Q for blocks >= 32768. Both 256-thread.
// ---------------------------------------------------------------------------
__global__ void vtrans_rope_kernel(const float* __restrict__ vc,
                                   float* __restrict__ vt,
                                   float* __restrict__ q)
{
    if (blockIdx.x < 32768) {
        __shared__ float t[32][33];
        int bx = blockIdx.x;
        int p0 = (bx & 31) * 32;
        int d0 = ((bx >> 5) & 3) * 32;
        int bh = bx >> 7;                    // 0..255
        const float* src = vc + (size_t)bh * KVLEN * HD;
        float* dst = vt + (size_t)bh * HD * KVLEN;
        int tx = threadIdx.x & 31, ty = threadIdx.x >> 5;   // 32 x 8
#pragma unroll
        for (int r = 0; r < 32; r += 8)
            t[ty + r][tx] = src[(size_t)(p0 + ty + r) * HD + d0 + tx];
        __syncthreads();
#pragma unroll
        for (int r = 0; r < 32; r += 8)
            dst[(size_t)(d0 + ty + r) * KVLEN + p0 + tx] = t[tx][ty + r];
    } else {
        int idx = (blockIdx.x - 32768) * 256 + threadIdx.x;
        const int total = NTOK * NHEADS * 64;
        if (idx >= total) return;
        int i   = idx & 63;
        int rest = idx >> 6;
        int h   = rest & (NHEADS - 1);
        int tok = rest >> 5;
        int s   = tok & (SEQ - 1);
        float pos = (float)(START_P + s);
        const float scale = 0.08838834764831845f;

        float freq = exp2f(-(float)i * 0.20762050593045702f);
        float ang = pos * freq;
        float c = cosf(ang), sn = sinf(ang);

        size_t base = (size_t)tok * DIM + h * HD + i;
        float q0 = q[base], q1 = q[base + 64];
        q[base]      = tf32r((q0 * c - q1 * sn) * scale);
        q[base + 64] = tf32r((q1 * c + q0 * sn) * scale);
    }
}

// ---------------------------------------------------------------------------
// Tensor-core flash attention v4: ldmatrix fragment loads throughout.
// Q/K stride 132 (ldsm row-quads 4r: conflict-free); V transposed [d][kv],
// tile [128][36] (row-quads 4r: conflict-free). Alternating K/V cp.async
// groups as before. Smem ~107 KB -> 2 blocks/SM.
// ---------------------------------------------------------------------------
#define AQ_ST   132
#define AK_ST   132
#define AVT_ST  36
#define KVT     32
#define AQ_FLOATS    (128 * AQ_ST)
#define AK_FLOATS    (KVT * AK_ST)
#define AVT_FLOATS   (128 * AVT_ST)
#define ATTN_SMEM_FLOATS (AQ_FLOATS + AK_FLOATS + AVT_FLOATS + KVLEN)

__global__ __launch_bounds__(256, 2) void attn_tc4_kernel(
    const float* __restrict__ qp, const float* __restrict__ kc,
    const float* __restrict__ vt, const float* __restrict__ radd_g,
    float* __restrict__ out)
{
    extern __shared__ float smem[];
    float* Qs  = smem;
    float* Ks  = smem + AQ_FLOATS;
    float* Vts = Ks + AK_FLOATS;
    float* radd_s = Vts + AVT_FLOATS;

    const int qt = blockIdx.x;
    const int h  = blockIdx.y;
    const int b  = blockIdx.z;
    const int tid = threadIdx.x;
    const int wid = tid >> 5;
    const int lane = tid & 31;
    const int grp = lane >> 2;
    const int t4 = lane & 3;
    const int lq = lane >> 3;
    const int lr = lane & 7;

    const float* qbase  = qp + (size_t)(b * SEQ + qt * 128) * DIM + h * HD;
    const float* kbase  = kc + ((size_t)(b * NHEADS + h)) * KVLEN * HD;
    const float* vtbase = vt + ((size_t)(b * NHEADS + h)) * HD * KVLEN;

#pragma unroll
    for (int p = 0; p < 16; p++) {
        int ci = tid + 256 * p;
        int r = ci >> 5, c = ci & 31;
        cp_async16(Qs + r * AQ_ST + c * 4, qbase + (size_t)r * DIM + c * 4);
    }
    cp_async16(radd_s + tid * 4, radd_g + (size_t)b * KVLEN + tid * 4);
#pragma unroll
    for (int p = 0; p < 4; p++) {
        int ci = tid + 256 * p;
        int r = ci >> 5, c = ci & 31;
        cp_async16(Ks + r * AK_ST + c * 4, kbase + (size_t)r * HD + c * 4);
    }
    CP_COMMIT();

    const unsigned sQ  = (unsigned)__cvta_generic_to_shared(Qs);
    const unsigned sK  = (unsigned)__cvta_generic_to_shared(Ks);
    const unsigned sVt = (unsigned)__cvta_generic_to_shared(Vts);

    float Oc[16][4];
#pragma unroll
    for (int nf = 0; nf < 16; nf++)
#pragma unroll
        for (int r = 0; r < 4; r++) Oc[nf][r] = 0.f;

    float mrun0 = -1e30f, mrun1 = -1e30f, lrun0 = 0.f, lrun1 = 0.f;
    const int m0 = wid * 16;
    const int qpos0 = START_P + qt * 128 + m0 + grp;
    const int qpos1 = qpos0 + 8;
    const int srcA = (lane & ~3) | (t4 >> 1);
    const int srcB = srcA + 2;
    // ldsm per-lane geometry
    const unsigned a_row = (unsigned)(m0 + (lq & 1) * 8 + lr);
    const unsigned a_col = (unsigned)((lq >> 1) * 4);
    const unsigned b_rowq = (unsigned)(lq >> 1);      // nf offset within pair
    const unsigned b_col = (unsigned)((lq & 1) * 4);

    for (int kt = 0; kt < KVLEN / KVT; kt++) {
        CP_WAIT0();
        __syncthreads();

        // issue Vt(kt) tile [128 d][32 kv]: overlaps S + softmax
#pragma unroll
        for (int p = 0; p < 4; p++) {
            int ci = tid + 256 * p;
            int r = ci >> 3, c = ci & 7;
            cp_async16(Vts + r * AVT_ST + c * 4,
                       vtbase + (size_t)r * KVLEN + kt * KVT + c * 4);
        }
        CP_COMMIT();

        // ---- S = Q K^T (ldsm fragments) ----
        float sc[4][4];
#pragma unroll
        for (int nf = 0; nf < 4; nf++)
#pragma unroll
            for (int r = 0; r < 4; r++) sc[nf][r] = 0.f;

#pragma unroll
        for (int ks = 0; ks < 16; ks++) {
            int ko = ks * 8;
            unsigned a4[4], bf[4][2];
            ldsm_x4(a4[0], a4[1], a4[2], a4[3],
                    sQ + (unsigned)((a_row * AQ_ST + ko + a_col) * 4));
            ldsm_x4(bf[0][0], bf[0][1], bf[1][0], bf[1][1],
                    sK + (unsigned)(((8 * b_rowq + lr) * AK_ST + ko + b_col) * 4));
            ldsm_x4(bf[2][0], bf[2][1], bf[3][0], bf[3][1],
                    sK + (unsigned)(((8 * (2 + b_rowq) + lr) * AK_ST + ko + b_col) * 4));
#pragma unroll
            for (int nf = 0; nf < 4; nf++)
                mma_tf32(sc[nf], a4, bf[nf]);
        }

        // ---- mask + online softmax ----
        float rmax0 = -1e30f, rmax1 = -1e30f;
#pragma unroll
        for (int nf = 0; nf < 4; nf++) {
#pragma unroll
            for (int e = 0; e < 2; e++) {
                int col = 8 * nf + 2 * t4 + e;
                int ng = kt * KVT + col;
                float add = radd_s[kt * KVT + col];
                float v0 = sc[nf][e]     + add + ((ng > qpos0) ? -1e9f : 0.f);
                float v1 = sc[nf][2 + e] + add + ((ng > qpos1) ? -1e9f : 0.f);
                sc[nf][e] = v0; sc[nf][2 + e] = v1;
                rmax0 = fmaxf(rmax0, v0);
                rmax1 = fmaxf(rmax1, v1);
            }
        }
        rmax0 = fmaxf(rmax0, __shfl_xor_sync(0xffffffffu, rmax0, 1));
        rmax0 = fmaxf(rmax0, __shfl_xor_sync(0xffffffffu, rmax0, 2));
        rmax1 = fmaxf(rmax1, __shfl_xor_sync(0xffffffffu, rmax1, 1));
        rmax1 = fmaxf(rmax1, __shfl_xor_sync(0xffffffffu, rmax1, 2));

        float mnew0 = fmaxf(mrun0, rmax0);
        float mnew1 = fmaxf(mrun1, rmax1);
        float alpha0 = __expf(mrun0 - mnew0);
        float alpha1 = __expf(mrun1 - mnew1);
        mrun0 = mnew0; mrun1 = mnew1;

        float ps0 = 0.f, ps1 = 0.f;
#pragma unroll
        for (int nf = 0; nf < 4; nf++) {
#pragma unroll
            for (int e = 0; e < 2; e++) {
                float p0 = __expf(sc[nf][e] - mnew0);
                float p1 = __expf(sc[nf][2 + e] - mnew1);
                ps0 += p0; ps1 += p1;
                sc[nf][e] = tf32r(p0);
                sc[nf][2 + e] = tf32r(p1);
            }
        }
        ps0 += __shfl_xor_sync(0xffffffffu, ps0, 1);
        ps0 += __shfl_xor_sync(0xffffffffu, ps0, 2);
        ps1 += __shfl_xor_sync(0xffffffffu, ps1, 1);
        ps1 += __shfl_xor_sync(0xffffffffu, ps1, 2);
        lrun0 = lrun0 * alpha0 + ps0;
        lrun1 = lrun1 * alpha1 + ps1;

#pragma unroll
        for (int nf = 0; nf < 16; nf++) {
            Oc[nf][0] *= alpha0; Oc[nf][1] *= alpha0;
            Oc[nf][2] *= alpha1; Oc[nf][3] *= alpha1;
        }

        CP_WAIT0();
        __syncthreads();

        // issue K(kt+1): overlaps PV
        if (kt + 1 < KVLEN / KVT) {
#pragma unroll
            for (int p = 0; p < 4; p++) {
                int ci = tid + 256 * p;
                int r = ci >> 5, c = ci & 31;
                cp_async16(Ks + r * AK_ST + c * 4,
                           kbase + (size_t)((kt + 1) * KVT + r) * HD + c * 4);
            }
        }
        CP_COMMIT();

        // ---- O += P V (P a-frags via quad shuffle; V b-frags via ldsm) ----
#pragma unroll
        for (int kcc = 0; kcc < 4; kcc++) {
            float x0 = __shfl_sync(0xffffffffu, sc[kcc][0], srcA);
            float x1 = __shfl_sync(0xffffffffu, sc[kcc][1], srcA);
            float y0 = __shfl_sync(0xffffffffu, sc[kcc][2], srcA);
            float y1 = __shfl_sync(0xffffffffu, sc[kcc][3], srcA);
            float x0b = __shfl_sync(0xffffffffu, sc[kcc][0], srcB);
            float x1b = __shfl_sync(0xffffffffu, sc[kcc][1], srcB);
            float y0b = __shfl_sync(0xffffffffu, sc[kcc][2], srcB);
            float y1b = __shfl_sync(0xffffffffu, sc[kcc][3], srcB);
            unsigned a[4];
            bool oddc = (t4 & 1);
            a[0] = __float_as_uint(oddc ? x1 : x0);
            a[1] = __float_as_uint(oddc ? y1 : y0);
            a[2] = __float_as_uint(oddc ? x1b : x0b);
            a[3] = __float_as_uint(oddc ? y1b : y0b);
            int ko = kcc * 8;
#pragma unroll
            for (int g4 = 0; g4 < 4; g4++) {
                int nfb = g4 * 4;
                unsigned bf[4][2];
                ldsm_x4(bf[0][0], bf[0][1], bf[1][0], bf[1][1],
                        sVt + (unsigned)(((8 * (nfb + b_rowq) + lr) * AVT_ST + ko + b_col) * 4));
                ldsm_x4(bf[2][0], bf[2][1], bf[3][0], bf[3][1],
                        sVt + (unsigned)(((8 * (nfb + 2 + b_rowq) + lr) * AVT_ST + ko + b_col) * 4));
#pragma unroll
                for (int j = 0; j < 4; j++)
                    mma_tf32(Oc[nfb + j], a, bf[j]);
            }
        }
    }

    float inv0 = 1.f / lrun0;
    float inv1 = 1.f / lrun1;
    int tok0 = b * SEQ + qt * 128 + m0 + grp;
#pragma unroll
    for (int nf = 0; nf < 16; nf++) {
        int col = h * HD + 8 * nf + 2 * t4;
        float2 v0 = make_float2(tf32r(Oc[nf][0] * inv0), tf32r(Oc[nf][1] * inv0));
        float2 v1 = make_float2(tf32r(Oc[nf][2] * inv1), tf32r(Oc[nf][3] * inv1));
        *(float2*)(out + (size_t)tok0 * DIM + col) = v0;
        *(float2*)(out + (size_t)(tok0 + 8) * DIM + col) = v1;
    }
}

// ---------------------------------------------------------------------------
extern "C" void kernel_launch(void* const* d_in, const int* in_sizes, int n_in,
                              void* d_out, int out_size)
{
    const float* x       = (const float*)d_in[0];
    const float* router  = (const float*)d_in[1];
    const float* cache_k = (const float*)d_in[2];
    const float* cache_v = (const float*)d_in[3];
    const float* wq      = (const float*)d_in[6];
    const float* wk      = (const float*)d_in[7];
    const float* wv      = (const float*)d_in[8];
    const float* wo      = (const float*)d_in[9];
    float* out = (float*)d_out;

    float *qp, *kp, *vp, *ap, *xr, *wqkvr, *wor, *kcp, *vcp, *vtp, *rap;
    cudaGetSymbolAddress((void**)&qp, g_q);
    cudaGetSymbolAddress((void**)&kp, g_k);
    cudaGetSymbolAddress((void**)&vp, g_v);
    cudaGetSymbolAddress((void**)&ap, g_attn);
    cudaGetSymbolAddress((void**)&xr, g_xr);
    cudaGetSymbolAddress((void**)&wqkvr, g_wqkvr);
    cudaGetSymbolAddress((void**)&wor, g_wor);
    cudaGetSymbolAddress((void**)&kcp, g_kc);
    cudaGetSymbolAddress((void**)&vcp, g_vc);
    cudaGetSymbolAddress((void**)&vtp, g_vt);
    cudaGetSymbolAddress((void**)&rap, g_radd);

    const int attn_smem = ATTN_SMEM_FLOATS * sizeof(float);   // ~107 KB
    cudaFuncSetAttribute(attn_tc4_kernel, cudaFuncAttributeMaxDynamicSharedMemorySize,
                         attn_smem);
    cudaFuncSetAttribute(sgemm_tf32_pipe, cudaFuncAttributeMaxDynamicSharedMemorySize,
                         GEMM_SMEM_BYTES);
    cudaFuncSetAttribute(sgemm_tf32_pipe_qkv, cudaFuncAttributeMaxDynamicSharedMemorySize,
                         GEMM_SMEM_BYTES);

    // pre-round x + weights to tf32 (wq/wk/wv into one concat buffer)
    {
        size_t n4 = (size_t)DIM * DIM / 4;
        int blocks = (int)((n4 + 255) / 256);
        round5_kernel<<<blocks, 256>>>(
            (const float4*)x, (const float4*)wq, (const float4*)wk,
            (const float4*)wv, (const float4*)wo,
            (float4*)xr, (float4*)wqkvr, (float4*)wor);
    }

    // merged QKV projection: one GEMM, N = 3*DIM
    {
        dim3 gg(3 * DIM / 128, NTOK / 128), gt(256);
        sgemm_tf32_pipe_qkv<<<gg, gt, GEMM_SMEM_BYTES>>>(xr, wqkvr, qp, kp, vp,
                                                         NTOK, DIM);
    }

    // K'/V' merge + rope + tf32, router mask
    {
        int total = BSZ * NHEADS * KVLEN * 64;
        prep_kv_kernel<<<(total + 255) / 256, 256>>>(
            kp, vp, cache_k, cache_v, router, kcp, vcp, rap);
    }
    // V transpose (vc -> vt) + Q rope in one launch
    vtrans_rope_kernel<<<65536, 256>>>(vcp, vtp, qp);

    {
        dim3 grid(SEQ / 128, NHEADS, BSZ);
        attn_tc4_kernel<<<grid, 256, attn_smem>>>(qp, kcp, vtp, rap, ap);
    }

    {
        dim3 gg(DIM / 128, NTOK / 128), gt(256);
        sgemm_tf32_pipe<<<gg, gt, GEMM_SMEM_BYTES>>>(ap, wor, out, NTOK, DIM, DIM);
    }
}

// round 17
// speedup vs baseline: 1.6572x; 1.6572x over previous
#include <cuda_runtime.h>
#include <cuda_fp16.h>
#include <cuda_bf16.h>
#include <math.h>

#define DIM     4096
#define NHEADS  32
#define HD      128
#define BSZ     8
#define SEQ     512
#define START_P 512
#define KVLEN   1024
#define NTOK    (BSZ*SEQ)   /* 4096 tokens */
#define MAXSEQ  2048

// Scratch (device globals; no runtime allocation allowed)
__device__ float g_q[(size_t)NTOK * DIM];
__device__ float g_k[(size_t)NTOK * DIM];
__device__ float g_v[(size_t)NTOK * DIM];
// fp16 operands
__device__ __half g_xh[(size_t)NTOK * DIM];
__device__ __half g_wqkvh[(size_t)3 * DIM * DIM];   // [wq; wk; wv]
__device__ __half g_woh[(size_t)DIM * DIM];
__device__ __half g_attnh[(size_t)NTOK * DIM];
// merged + tf32-rounded K/V for attention, router mask
__device__ float g_kc[(size_t)BSZ * NHEADS * KVLEN * HD];
__device__ float g_vc[(size_t)BSZ * NHEADS * KVLEN * HD];
__device__ float g_radd[(size_t)BSZ * KVLEN];

// ---------------------------------------------------------------------------
// helpers
// ---------------------------------------------------------------------------
__device__ __forceinline__ float tf32r(float x) {
    float y;
    asm("cvt.rna.tf32.f32 %0, %1;" : "=f"(y) : "f"(x));
    return y;
}

__device__ __forceinline__ void mma_tf32(float* c, const unsigned* a, const unsigned* b) {
    asm volatile(
        "mma.sync.aligned.m16n8k8.row.col.f32.tf32.tf32.f32 "
        "{%0,%1,%2,%3}, {%4,%5,%6,%7}, {%8,%9}, {%0,%1,%2,%3};"
        : "+f"(c[0]), "+f"(c[1]), "+f"(c[2]), "+f"(c[3])
        : "r"(a[0]), "r"(a[1]), "r"(a[2]), "r"(a[3]),
          "r"(b[0]), "r"(b[1]));
}

__device__ __forceinline__ void mma_f16(float* c, const unsigned* a, const unsigned* b) {
    asm volatile(
        "mma.sync.aligned.m16n8k16.row.col.f32.f16.f16.f32 "
        "{%0,%1,%2,%3}, {%4,%5,%6,%7}, {%8,%9}, {%0,%1,%2,%3};"
        : "+f"(c[0]), "+f"(c[1]), "+f"(c[2]), "+f"(c[3])
        : "r"(a[0]), "r"(a[1]), "r"(a[2]), "r"(a[3]),
          "r"(b[0]), "r"(b[1]));
}

__device__ __forceinline__ void ldsm_x4(unsigned& r0, unsigned& r1,
                                        unsigned& r2, unsigned& r3,
                                        unsigned saddr) {
    asm volatile(
        "ldmatrix.sync.aligned.m8n8.x4.shared.b16 {%0,%1,%2,%3}, [%4];"
        : "=r"(r0), "=r"(r1), "=r"(r2), "=r"(r3)
        : "r"(saddr));
}

__device__ __forceinline__ void cp_async16(void* smem_dst, const void* gsrc) {
    unsigned saddr = (unsigned)__cvta_generic_to_shared(smem_dst);
    asm volatile("cp.async.cg.shared.global [%0], [%1], 16;\n"
                 :: "r"(saddr), "l"(gsrc));
}
#define CP_COMMIT() asm volatile("cp.async.commit_group;\n" ::: "memory")
#define CP_WAIT1()  asm volatile("cp.async.wait_group 1;\n" ::: "memory")
#define CP_WAIT0()  asm volatile("cp.async.wait_group 0;\n" ::: "memory")

__device__ __forceinline__ unsigned pack_h2(float a, float b) {
    __half2 h = __floats2half2_rn(a, b);
    return *(unsigned*)&h;
}

// ---------------------------------------------------------------------------
// Convert x, [wq;wk;wv], wo to fp16.
// ---------------------------------------------------------------------------
__global__ void convert5_kernel(
    const float4* __restrict__ x,  const float4* __restrict__ wq,
    const float4* __restrict__ wk, const float4* __restrict__ wv,
    const float4* __restrict__ wo,
    uint2* __restrict__ xh, uint2* __restrict__ wqkvh, uint2* __restrict__ woh)
{
    size_t i = (size_t)blockIdx.x * blockDim.x + threadIdx.x;
    const size_t n = (size_t)DIM * DIM / 4;
    if (i >= n) return;
#define C4(dst, src) { float4 v = src[i]; \
    uint2 o; o.x = pack_h2(v.x, v.y); o.y = pack_h2(v.z, v.w); dst = o; }
    C4(xh[i], x)
    C4(wqkvh[i], wq)
    C4(wqkvh[i + n], wk)
    C4(wqkvh[i + 2 * n], wv)
    C4(woh[i], wo)
#undef C4
}

// ---------------------------------------------------------------------------
// FP16 tensor-core GEMM NT: C = A B^T, fp32 accumulate.
// Block 128x128, BK=64 (128-byte rows, same XOR swizzle as tf32 version),
// 256 thr, 8 warps (2m x 4n), warp tile 64x32, mma m16n8k16.f16.
// ldmatrix fragments; single barrier per k-tile; refill after compute;
// 3-stage cp.async ring (32KB/stage = 96KB).
// ---------------------------------------------------------------------------
#define GH_STAGE_HALVES (2 * 128 * 64)                     /* 16384 */
#define GH_SMEM_BYTES (3 * GH_STAGE_HALVES * 2)            /* 96 KB */

#define GEMMH_BODY(A_, B_, K_)                                                 \
    extern __shared__ __half smh[];                                            \
    const int tid = threadIdx.x;                                               \
    const int bm = blockIdx.y * 128;                                           \
    const int bn = blockIdx.x * 128;                                           \
    const int warp = tid >> 5, lane = tid & 31;                                \
    const int wm = warp >> 2;                                                  \
    const int wn = warp & 3;                                                   \
    const int grp = lane >> 2;                                                 \
    const int t4 = lane & 3;                                                   \
    const int lq = lane >> 3;                                                  \
    const int lr = lane & 7;                                                   \
    const int a_half = lq & 1;                                                 \
    const int a_chi  = lq >> 1;                                                \
    const int b_nfq  = lq >> 1;                                                \
    const int b_csel = lq & 1;                                                 \
    int abyte[4];                                                              \
    _Pragma("unroll")                                                          \
    for (int mf = 0; mf < 4; mf++)                                             \
        abyte[mf] = (wm * 64 + mf * 16 + a_half * 8 + lr) * 128;               \
    const int bbyte0 = (wn * 32 + b_nfq * 8 + lr) * 128;                       \
    const int bbyte1 = (wn * 32 + (2 + b_nfq) * 8 + lr) * 128;                 \
    int pr[4], pc[4], poff[4];                                                 \
    _Pragma("unroll")                                                          \
    for (int p = 0; p < 4; p++) {                                              \
        int ci = tid + 256 * p;                                                \
        pr[p] = ci >> 3;                                                       \
        pc[p] = ci & 7;                                                        \
        poff[p] = pr[p] * 64 + ((pc[p] ^ (pr[p] & 7)) << 3);                   \
    }                                                                          \
    float acc[4][4][4];                                                        \
    _Pragma("unroll")                                                          \
    for (int mf = 0; mf < 4; mf++)                                             \
        for (int nf = 0; nf < 4; nf++)                                         \
            for (int r = 0; r < 4; r++) acc[mf][nf][r] = 0.f;                  \
    const int KT = (K_) / 64;                                                  \
    _Pragma("unroll")                                                          \
    for (int s = 0; s < 2; s++) {                                              \
        __half* As = smh + s * GH_STAGE_HALVES;                                \
        __half* Bs = As + 128 * 64;                                            \
        int k0 = s * 64;                                                       \
        _Pragma("unroll")                                                      \
        for (int p = 0; p < 4; p++) {                                          \
            cp_async16(As + poff[p], (A_) + (size_t)(bm + pr[p]) * (K_) + k0 + pc[p] * 8); \
            cp_async16(Bs + poff[p], (B_) + (size_t)(bn + pr[p]) * (K_) + k0 + pc[p] * 8); \
        }                                                                      \
        CP_COMMIT();                                                           \
    }                                                                          \
    for (int kt = 0; kt < KT; kt++) {                                          \
        CP_WAIT1();                                                            \
        __syncthreads();                                                       \
        const __half* Asp = smh + (kt % 3) * GH_STAGE_HALVES;                  \
        const unsigned sA = (unsigned)__cvta_generic_to_shared(Asp);           \
        const unsigned sB = sA + 128 * 64 * 2;                                 \
        _Pragma("unroll")                                                      \
        for (int ks = 0; ks < 4; ks++) {                                       \
            const unsigned aoff = (unsigned)(((2 * ks + a_chi) ^ lr) << 4);    \
            const unsigned boff = (unsigned)(((2 * ks + b_csel) ^ lr) << 4);   \
            unsigned af[4][4], bf[4][2];                                       \
            _Pragma("unroll")                                                  \
            for (int mf = 0; mf < 4; mf++)                                     \
                ldsm_x4(af[mf][0], af[mf][1], af[mf][2], af[mf][3],            \
                        sA + abyte[mf] + aoff);                                \
            ldsm_x4(bf[0][0], bf[0][1], bf[1][0], bf[1][1], sB + bbyte0 + boff); \
            ldsm_x4(bf[2][0], bf[2][1], bf[3][0], bf[3][1], sB + bbyte1 + boff); \
            _Pragma("unroll")                                                  \
            for (int mf = 0; mf < 4; mf++)                                     \
                for (int nf = 0; nf < 4; nf++)                                 \
                    mma_f16(acc[mf][nf], af[mf], bf[nf]);                      \
        }                                                                      \
        if (kt + 2 < KT) {                                                     \
            int s = (kt + 2) % 3;                                              \
            __half* Asw = smh + s * GH_STAGE_HALVES;                           \
            __half* Bsw = Asw + 128 * 64;                                      \
            int k0 = (kt + 2) * 64;                                            \
            _Pragma("unroll")                                                  \
            for (int p = 0; p < 4; p++) {                                      \
                cp_async16(Asw + poff[p], (A_) + (size_t)(bm + pr[p]) * (K_) + k0 + pc[p] * 8); \
                cp_async16(Bsw + poff[p], (B_) + (size_t)(bn + pr[p]) * (K_) + k0 + pc[p] * 8); \
            }                                                                  \
        }                                                                      \
        CP_COMMIT();                                                           \
    }

__global__ __launch_bounds__(256, 2) void hgemm_pipe(
    const __half* __restrict__ A, const __half* __restrict__ B,
    float* __restrict__ C, int M, int N, int K)
{
    GEMMH_BODY(A, B, K)
#pragma unroll
    for (int mf = 0; mf < 4; mf++) {
        int row0 = bm + wm * 64 + mf * 16 + grp;
#pragma unroll
        for (int nf = 0; nf < 4; nf++) {
            int col0 = bn + wn * 32 + nf * 8 + t4 * 2;
            float2 v0 = make_float2(acc[mf][nf][0], acc[mf][nf][1]);
            float2 v1 = make_float2(acc[mf][nf][2], acc[mf][nf][3]);
            *(float2*)(C + (size_t)row0 * N + col0) = v0;
            *(float2*)(C + (size_t)(row0 + 8) * N + col0) = v1;
        }
    }
}

__global__ __launch_bounds__(256, 2) void hgemm_pipe_qkv(
    const __half* __restrict__ A, const __half* __restrict__ B,
    float* __restrict__ Cq, float* __restrict__ Ck, float* __restrict__ Cv,
    int M, int K)
{
    GEMMH_BODY(A, B, K)
    const int which = bn >> 12;
    float* Cw = (which == 0) ? Cq : (which == 1) ? Ck : Cv;
    const int cb = bn & (DIM - 1);
#pragma unroll
    for (int mf = 0; mf < 4; mf++) {
        int row0 = bm + wm * 64 + mf * 16 + grp;
#pragma unroll
        for (int nf = 0; nf < 4; nf++) {
            int col0 = cb + wn * 32 + nf * 8 + t4 * 2;
            float2 v0 = make_float2(acc[mf][nf][0], acc[mf][nf][1]);
            float2 v1 = make_float2(acc[mf][nf][2], acc[mf][nf][3]);
            *(float2*)(Cw + (size_t)row0 * DIM + col0) = v0;
            *(float2*)(Cw + (size_t)(row0 + 8) * DIM + col0) = v1;
        }
    }
}

// ---------------------------------------------------------------------------
// RoPE + scale + tf32-round Q in place.
// ---------------------------------------------------------------------------
__global__ void rope_q_kernel(float* __restrict__ q)
{
    int idx = blockIdx.x * blockDim.x + threadIdx.x;
    const int total = NTOK * NHEADS * 64;
    if (idx >= total) return;
    int i   = idx & 63;
    int rest = idx >> 6;
    int h   = rest & (NHEADS - 1);
    int tok = rest >> 5;
    int s   = tok & (SEQ - 1);
    float pos = (float)(START_P + s);
    const float scale = 0.08838834764831845f;

    float freq = exp2f(-(float)i * 0.20762050593045702f);
    float ang = pos * freq;
    float c = cosf(ang), sn = sinf(ang);

    size_t base = (size_t)tok * DIM + h * HD + i;
    float q0 = q[base], q1 = q[base + 64];
    q[base]      = tf32r((q0 * c - q1 * sn) * scale);
    q[base + 64] = tf32r((q1 * c + q0 * sn) * scale);
}

// ---------------------------------------------------------------------------
// Build merged tf32 K'/V' [b][h][1024][128] + router additive mask.
// ---------------------------------------------------------------------------
__global__ void prep_kv_kernel(
    const float* __restrict__ knew, const float* __restrict__ vnew,
    const float* __restrict__ cache_k, const float* __restrict__ cache_v,
    const float* __restrict__ router,
    float* __restrict__ kc, float* __restrict__ vc, float* __restrict__ radd)
{
    int idx = blockIdx.x * blockDim.x + threadIdx.x;
    const int total = BSZ * NHEADS * KVLEN * 64;
    if (idx >= total) return;
    int i   = idx & 63;
    int pos = (idx >> 6) & (KVLEN - 1);
    int h   = (idx >> 16) & (NHEADS - 1);
    int b   = idx >> 21;

    size_t dst = (((size_t)(b * NHEADS + h)) * KVLEN + pos) * HD + i;
    if (pos < START_P) {
        size_t src = (((size_t)(b * NHEADS + h)) * MAXSEQ + pos) * HD + i;
        kc[dst]      = tf32r(cache_k[src]);
        kc[dst + 64] = tf32r(cache_k[src + 64]);
        vc[dst]      = tf32r(cache_v[src]);
        vc[dst + 64] = tf32r(cache_v[src + 64]);
    } else {
        int s = pos - START_P;
        size_t src = ((size_t)(b * SEQ + s)) * DIM + h * HD + i;
        float freq = exp2f(-(float)i * 0.20762050593045702f);
        float ang = (float)pos * freq;
        float c = cosf(ang), sn = sinf(ang);
        float k0 = knew[src], k1 = knew[src + 64];
        kc[dst]      = tf32r(k0 * c - k1 * sn);
        kc[dst + 64] = tf32r(k1 * c + k0 * sn);
        vc[dst]      = tf32r(vnew[src]);
        vc[dst + 64] = tf32r(vnew[src + 64]);
    }
    if (h == 0 && i == 0) {
        float add = 0.f;
        if (pos >= START_P &&
            router[((size_t)b * SEQ + (pos - START_P)) * 2] == 0.f) add = -1e9f;
        radd[(size_t)b * KVLEN + pos] = add;
    }
}

// ---------------------------------------------------------------------------
// Tensor-core flash attention v3 (R15 version). Epilogue emits fp16 for the
// WO fp16 GEMM. 103.5 KB smem -> 2 blocks/SM; alternating K/V cp.async.
// ---------------------------------------------------------------------------
#define AQ_ST  132
#define AK_ST  132
#define AV_ST  136
#define KVT    32
#define AQ_FLOATS   (128 * AQ_ST)
#define AK_FLOATS   (KVT * AK_ST)
#define AV_FLOATS   (KVT * AV_ST)
#define ATTN_SMEM_FLOATS (AQ_FLOATS + AK_FLOATS + AV_FLOATS + KVLEN)

__global__ __launch_bounds__(256, 2) void attn_tc3_kernel(
    const float* __restrict__ qp, const float* __restrict__ kc,
    const float* __restrict__ vc, const float* __restrict__ radd_g,
    __half* __restrict__ outh)
{
    extern __shared__ float smem[];
    float* Qs = smem;
    float* Ks = smem + AQ_FLOATS;
    float* Vs = Ks + AK_FLOATS;
    float* radd_s = Vs + AV_FLOATS;

    const int qt = blockIdx.x;
    const int h  = blockIdx.y;
    const int b  = blockIdx.z;
    const int tid = threadIdx.x;
    const int wid = tid >> 5;
    const int lane = tid & 31;
    const int grp = lane >> 2;
    const int t4 = lane & 3;

    const float* qbase = qp + (size_t)(b * SEQ + qt * 128) * DIM + h * HD;
    const float* kbase = kc + ((size_t)(b * NHEADS + h)) * KVLEN * HD;
    const float* vbase = vc + ((size_t)(b * NHEADS + h)) * KVLEN * HD;

#pragma unroll
    for (int p = 0; p < 16; p++) {
        int ci = tid + 256 * p;
        int r = ci >> 5, c = ci & 31;
        cp_async16(Qs + r * AQ_ST + c * 4, qbase + (size_t)r * DIM + c * 4);
    }
    cp_async16(radd_s + tid * 4, radd_g + (size_t)b * KVLEN + tid * 4);
#pragma unroll
    for (int p = 0; p < 4; p++) {
        int ci = tid + 256 * p;
        int r = ci >> 5, c = ci & 31;
        cp_async16(Ks + r * AK_ST + c * 4, kbase + (size_t)r * HD + c * 4);
    }
    CP_COMMIT();

    float Oc[16][4];
#pragma unroll
    for (int nf = 0; nf < 16; nf++)
#pragma unroll
        for (int r = 0; r < 4; r++) Oc[nf][r] = 0.f;

    float mrun0 = -1e30f, mrun1 = -1e30f, lrun0 = 0.f, lrun1 = 0.f;
    const int m0 = wid * 16;
    const int qpos0 = START_P + qt * 128 + m0 + grp;
    const int qpos1 = qpos0 + 8;
    const int srcA = (lane & ~3) | (t4 >> 1);
    const int srcB = srcA + 2;

    for (int kt = 0; kt < KVLEN / KVT; kt++) {
        CP_WAIT0();
        __syncthreads();

#pragma unroll
        for (int p = 0; p < 4; p++) {
            int ci = tid + 256 * p;
            int r = ci >> 5, c = ci & 31;
            cp_async16(Vs + r * AV_ST + c * 4,
                       vbase + (size_t)(kt * KVT + r) * HD + c * 4);
        }
        CP_COMMIT();

        float sc[4][4];
#pragma unroll
        for (int nf = 0; nf < 4; nf++)
#pragma unroll
            for (int r = 0; r < 4; r++) sc[nf][r] = 0.f;

#pragma unroll
        for (int ks = 0; ks < 16; ks++) {
            int ko = ks * 8;
            unsigned a[4];
            a[0] = __float_as_uint(Qs[(m0 + grp) * AQ_ST + ko + t4]);
            a[1] = __float_as_uint(Qs[(m0 + grp + 8) * AQ_ST + ko + t4]);
            a[2] = __float_as_uint(Qs[(m0 + grp) * AQ_ST + ko + t4 + 4]);
            a[3] = __float_as_uint(Qs[(m0 + grp + 8) * AQ_ST + ko + t4 + 4]);
#pragma unroll
            for (int nf = 0; nf < 4; nf++) {
                unsigned bb[2];
                bb[0] = __float_as_uint(Ks[(8 * nf + grp) * AK_ST + ko + t4]);
                bb[1] = __float_as_uint(Ks[(8 * nf + grp) * AK_ST + ko + t4 + 4]);
                mma_tf32(sc[nf], a, bb);
            }
        }

        float rmax0 = -1e30f, rmax1 = -1e30f;
#pragma unroll
        for (int nf = 0; nf < 4; nf++) {
#pragma unroll
            for (int e = 0; e < 2; e++) {
                int col = 8 * nf + 2 * t4 + e;
                int ng = kt * KVT + col;
                float add = radd_s[kt * KVT + col];
                float v0 = sc[nf][e]     + add + ((ng > qpos0) ? -1e9f : 0.f);
                float v1 = sc[nf][2 + e] + add + ((ng > qpos1) ? -1e9f : 0.f);
                sc[nf][e] = v0; sc[nf][2 + e] = v1;
                rmax0 = fmaxf(rmax0, v0);
                rmax1 = fmaxf(rmax1, v1);
            }
        }
        rmax0 = fmaxf(rmax0, __shfl_xor_sync(0xffffffffu, rmax0, 1));
        rmax0 = fmaxf(rmax0, __shfl_xor_sync(0xffffffffu, rmax0, 2));
        rmax1 = fmaxf(rmax1, __shfl_xor_sync(0xffffffffu, rmax1, 1));
        rmax1 = fmaxf(rmax1, __shfl_xor_sync(0xffffffffu, rmax1, 2));

        float mnew0 = fmaxf(mrun0, rmax0);
        float mnew1 = fmaxf(mrun1, rmax1);
        float alpha0 = __expf(mrun0 - mnew0);
        float alpha1 = __expf(mrun1 - mnew1);
        mrun0 = mnew0; mrun1 = mnew1;

        float ps0 = 0.f, ps1 = 0.f;
#pragma unroll
        for (int nf = 0; nf < 4; nf++) {
#pragma unroll
            for (int e = 0; e < 2; e++) {
                float p0 = __expf(sc[nf][e] - mnew0);
                float p1 = __expf(sc[nf][2 + e] - mnew1);
                ps0 += p0; ps1 += p1;
                sc[nf][e] = tf32r(p0);
                sc[nf][2 + e] = tf32r(p1);
            }
        }
        ps0 += __shfl_xor_sync(0xffffffffu, ps0, 1);
        ps0 += __shfl_xor_sync(0xffffffffu, ps0, 2);
        ps1 += __shfl_xor_sync(0xffffffffu, ps1, 1);
        ps1 += __shfl_xor_sync(0xffffffffu, ps1, 2);
        lrun0 = lrun0 * alpha0 + ps0;
        lrun1 = lrun1 * alpha1 + ps1;

#pragma unroll
        for (int nf = 0; nf < 16; nf++) {
            Oc[nf][0] *= alpha0; Oc[nf][1] *= alpha0;
            Oc[nf][2] *= alpha1; Oc[nf][3] *= alpha1;
        }

        CP_WAIT0();
        __syncthreads();

        if (kt + 1 < KVLEN / KVT) {
#pragma unroll
            for (int p = 0; p < 4; p++) {
                int ci = tid + 256 * p;
                int r = ci >> 5, c = ci & 31;
                cp_async16(Ks + r * AK_ST + c * 4,
                           kbase + (size_t)((kt + 1) * KVT + r) * HD + c * 4);
            }
        }
        CP_COMMIT();

#pragma unroll
        for (int kcc = 0; kcc < 4; kcc++) {
            float x0 = __shfl_sync(0xffffffffu, sc[kcc][0], srcA);
            float x1 = __shfl_sync(0xffffffffu, sc[kcc][1], srcA);
            float y0 = __shfl_sync(0xffffffffu, sc[kcc][2], srcA);
            float y1 = __shfl_sync(0xffffffffu, sc[kcc][3], srcA);
            float x0b = __shfl_sync(0xffffffffu, sc[kcc][0], srcB);
            float x1b = __shfl_sync(0xffffffffu, sc[kcc][1], srcB);
            float y0b = __shfl_sync(0xffffffffu, sc[kcc][2], srcB);
            float y1b = __shfl_sync(0xffffffffu, sc[kcc][3], srcB);
            unsigned a[4];
            bool oddc = (t4 & 1);
            a[0] = __float_as_uint(oddc ? x1 : x0);
            a[1] = __float_as_uint(oddc ? y1 : y0);
            a[2] = __float_as_uint(oddc ? x1b : x0b);
            a[3] = __float_as_uint(oddc ? y1b : y0b);
            int ko = kcc * 8;
#pragma unroll
            for (int nf = 0; nf < 16; nf++) {
                unsigned bb[2];
                bb[0] = __float_as_uint(Vs[(ko + t4) * AV_ST + 8 * nf + grp]);
                bb[1] = __float_as_uint(Vs[(ko + t4 + 4) * AV_ST + 8 * nf + grp]);
                mma_tf32(Oc[nf], a, bb);
            }
        }
    }

    // ---- normalize + fp16 store (feeds WO fp16 GEMM) ----
    float inv0 = 1.f / lrun0;
    float inv1 = 1.f / lrun1;
    int tok0 = b * SEQ + qt * 128 + m0 + grp;
    unsigned* outw = (unsigned*)outh;
#pragma unroll
    for (int nf = 0; nf < 16; nf++) {
        int col = h * HD + 8 * nf + 2 * t4;   // even
        size_t w0 = ((size_t)tok0 * DIM + col) >> 1;
        size_t w1 = ((size_t)(tok0 + 8) * DIM + col) >> 1;
        outw[w0] = pack_h2(Oc[nf][0] * inv0, Oc[nf][1] * inv0);
        outw[w1] = pack_h2(Oc[nf][2] * inv1, Oc[nf][3] * inv1);
    }
}

// ---------------------------------------------------------------------------
extern "C" void kernel_launch(void* const* d_in, const int* in_sizes, int n_in,
                              void* d_out, int out_size)
{
    const float* x       = (const float*)d_in[0];
    const float* router  = (const float*)d_in[1];
    const float* cache_k = (const float*)d_in[2];
    const float* cache_v = (const float*)d_in[3];
    const float* wq      = (const float*)d_in[6];
    const float* wk      = (const float*)d_in[7];
    const float* wv      = (const float*)d_in[8];
    const float* wo      = (const float*)d_in[9];
    float* out = (float*)d_out;

    float *qp, *kp, *vp, *kcp, *vcp, *rap;
    __half *xh, *wqkvh, *woh, *ah;
    cudaGetSymbolAddress((void**)&qp, g_q);
    cudaGetSymbolAddress((void**)&kp, g_k);
    cudaGetSymbolAddress((void**)&vp, g_v);
    cudaGetSymbolAddress((void**)&kcp, g_kc);
    cudaGetSymbolAddress((void**)&vcp, g_vc);
    cudaGetSymbolAddress((void**)&rap, g_radd);
    cudaGetSymbolAddress((void**)&xh, g_xh);
    cudaGetSymbolAddress((void**)&wqkvh, g_wqkvh);
    cudaGetSymbolAddress((void**)&woh, g_woh);
    cudaGetSymbolAddress((void**)&ah, g_attnh);

    const int attn_smem = ATTN_SMEM_FLOATS * sizeof(float);
    cudaFuncSetAttribute(attn_tc3_kernel, cudaFuncAttributeMaxDynamicSharedMemorySize,
                         attn_smem);
    cudaFuncSetAttribute(hgemm_pipe, cudaFuncAttributeMaxDynamicSharedMemorySize,
                         GH_SMEM_BYTES);
    cudaFuncSetAttribute(hgemm_pipe_qkv, cudaFuncAttributeMaxDynamicSharedMemorySize,
                         GH_SMEM_BYTES);

    // convert x + weights to fp16 (wq/wk/wv into one concat buffer)
    {
        size_t n4 = (size_t)DIM * DIM / 4;
        int blocks = (int)((n4 + 255) / 256);
        convert5_kernel<<<blocks, 256>>>(
            (const float4*)x, (const float4*)wq, (const float4*)wk,
            (const float4*)wv, (const float4*)wo,
            (uint2*)xh, (uint2*)wqkvh, (uint2*)woh);
    }

    // merged QKV projection: one fp16 GEMM, N = 3*DIM
    {
        dim3 gg(3 * DIM / 128, NTOK / 128), gt(256);
        hgemm_pipe_qkv<<<gg, gt, GH_SMEM_BYTES>>>(xh, wqkvh, qp, kp, vp,
                                                  NTOK, DIM);
    }

    // Q: rope+scale+tf32 in place
    {
        int total = NTOK * NHEADS * 64;
        rope_q_kernel<<<(total + 255) / 256, 256>>>(qp);
    }
    // K'/V' merge + rope + tf32, router mask
    {
        int total = BSZ * NHEADS * KVLEN * 64;
        prep_kv_kernel<<<(total + 255) / 256, 256>>>(
            kp, vp, cache_k, cache_v, router, kcp, vcp, rap);
    }

    {
        dim3 grid(SEQ / 128, NHEADS, BSZ);
        attn_tc3_kernel<<<grid, 256, attn_smem>>>(qp, kcp, vcp, rap, ah);
    }

    {
        dim3 gg(DIM / 128, NTOK / 128), gt(256);
        hgemm_pipe<<<gg, gt, GH_SMEM_BYTES>>>(ah, woh, out, NTOK, DIM, DIM);
    }
}